// round 8
// baseline (speedup 1.0000x reference)
#include <cuda_runtime.h>
#include <cuda_fp16.h>
#include <cstdint>

// ---------------------------------------------------------------------------
// out[8192,4096] = x[8192,4096]_fp32 @ sign(fp16(w[4096,4096]))
//
// R8: two-level int8 IMMA path.
//   x ~= s1[m]*q1 + (s1[m]/256)*q2   (q1,q2 int8, exact s32 GEMMs)
//   wb = sign(fp16(w)) in int8 {-1,0,1}, transposed [N,K]
//   out = s1[m] * ( float(q1@wb) + float(q2@wb)/256 )
// mma.sync.m16n8k32.s32.s8.s8.s32 (2x fp16 rate, no fp-accumulate penalty).
// 4-stage cp.async + mbarrier pipeline (proven in R7).
// ---------------------------------------------------------------------------

#define M_DIM 8192
#define N_DIM 4096
#define K_DIM 4096

#define BM 128
#define BN 128
#define BK 128                 // int8: 128 bytes per row (one swizzle atom)
#define STAGES 4
#define THREADS 512
#define NKI (K_DIM / BK)       // 32

#define A_PLANE_BYTES (BM * BK)                    // 16384 per plane
#define A_TILE_BYTES  (2 * A_PLANE_BYTES)          // q1 + q2 = 32768
#define B_TILE_BYTES  (BN * BK)                    // 16384
#define STAGE_BYTES   (A_TILE_BYTES + B_TILE_BYTES)  // 49152
#define SMEM_DYN      (1024 + 1024 + STAGES * STAGE_BYTES)  // 198656

// ------------------------------ scratch -----------------------------------
__device__ __align__(1024) int8_t g_q1[(size_t)M_DIM * K_DIM];   // 32 MB
__device__ __align__(1024) int8_t g_q2[(size_t)M_DIM * K_DIM];   // 32 MB
__device__ __align__(1024) int8_t g_wbt[(size_t)N_DIM * K_DIM];  // 16 MB
__device__ float g_s1[M_DIM];

// --------------------------- quantize x ------------------------------------
// one block per row: maxabs reduce, then two-level int8 quantization
__global__ void __launch_bounds__(256, 4) quant_x_kernel(
    const float4* __restrict__ x, char4* __restrict__ q1,
    char4* __restrict__ q2, float* __restrict__ s1out)
{
    __shared__ float red[8];
    const int row = blockIdx.x;
    const int t   = threadIdx.x;
    const size_t base = (size_t)row * (K_DIM / 4);

    float4 v[4];
    float mx = 0.f;
    #pragma unroll
    for (int c = 0; c < 4; c++) {
        v[c] = x[base + c * 256 + t];
        mx = fmaxf(mx, fmaxf(fmaxf(fabsf(v[c].x), fabsf(v[c].y)),
                             fmaxf(fabsf(v[c].z), fabsf(v[c].w))));
    }
    #pragma unroll
    for (int o = 16; o > 0; o >>= 1)
        mx = fmaxf(mx, __shfl_xor_sync(0xFFFFFFFF, mx, o));
    if ((t & 31) == 0) red[t >> 5] = mx;
    __syncthreads();
    if (t < 8) {
        float m = red[t];
        #pragma unroll
        for (int o = 4; o > 0; o >>= 1)
            m = fmaxf(m, __shfl_xor_sync(0xFF, m, o));
        if (t == 0) red[0] = fmaxf(m, 1e-20f);
    }
    __syncthreads();
    const float maxabs = red[0];
    const float s1   = maxabs * (1.0f / 127.0f);
    const float inv1 = 127.0f / maxabs;
    const float inv2 = inv1 * 256.0f;
    if (t == 0) s1out[row] = s1;

    #pragma unroll
    for (int c = 0; c < 4; c++) {
        float xs[4] = {v[c].x, v[c].y, v[c].z, v[c].w};
        char b1[4], b2[4];
        #pragma unroll
        for (int j = 0; j < 4; j++) {
            int i1 = __float2int_rn(xs[j] * inv1);
            float r = fmaf((float)(-i1), s1, xs[j]);   // exact-ish residual
            int i2 = __float2int_rn(r * inv2);
            i2 = max(-128, min(127, i2));
            b1[j] = (char)i1;
            b2[j] = (char)i2;
        }
        q1[base + c * 256 + t] = make_char4(b1[0], b1[1], b1[2], b1[3]);
        q2[base + c * 256 + t] = make_char4(b2[0], b2[1], b2[2], b2[3]);
    }
}

// w[K,N] fp32 -> wbt[N,K] int8 with value sign(fp16(w)) (sign(0) = 0)
__global__ void cvt_w_kernel(const float* __restrict__ w, int8_t* __restrict__ wbt) {
    __shared__ int8_t tile[32][33];
    int n0 = blockIdx.x * 32;
    int k0 = blockIdx.y * 32;
    int tx = threadIdx.x, ty = threadIdx.y;
    #pragma unroll
    for (int j = ty; j < 32; j += 8) {
        float v = w[(size_t)(k0 + j) * N_DIM + n0 + tx];
        float hf = __half2float(__float2half_rn(v));  // exact fp16 round trip
        tile[j][tx] = (hf > 0.f) ? 1 : ((hf < 0.f) ? -1 : 0);
    }
    __syncthreads();
    #pragma unroll
    for (int j = ty; j < 32; j += 8) {
        wbt[(size_t)(n0 + j) * K_DIM + k0 + tx] = tile[tx][j];
    }
}

// dummy launch to keep ncu's -s window on the GEMM (position 3)
__global__ void prof_pad_kernel() {}

// ------------------------------ PTX helpers -------------------------------
__device__ __forceinline__ uint32_t smem_u32(const void* p) {
    uint32_t a;
    asm("{ .reg .u64 t; cvta.to.shared.u64 t, %1; cvt.u32.u64 %0, t; }"
        : "=r"(a) : "l"(p));
    return a;
}

__device__ __forceinline__ void cp_async_16(uint32_t smem_dst, const void* gmem_src) {
    asm volatile("cp.async.cg.shared.global [%0], [%1], 16;"
                 :: "r"(smem_dst), "l"(gmem_src));
}

#define MBARRIER_INIT(addr, count) \
    asm volatile("mbarrier.init.shared.b64 [%0], %1;" \
                 :: "r"((uint32_t)(addr)), "r"((uint32_t)(count)) : "memory")

#define MBARRIER_ARRIVE(addr) \
    asm volatile("mbarrier.arrive.shared.b64 _, [%0];" \
                 :: "r"((uint32_t)(addr)) : "memory")

#define CPASYNC_MBAR_ARRIVE_NOINC(addr) \
    asm volatile("cp.async.mbarrier.arrive.noinc.shared.b64 [%0];" \
                 :: "r"((uint32_t)(addr)) : "memory")

#define MBARRIER_WAIT_PARITY(mbar_smem_addr, phase_parity) do { \
    uint32_t _mbar = (uint32_t)(mbar_smem_addr); \
    uint32_t _parity = (uint32_t)(phase_parity); \
    uint32_t _done; \
    asm volatile( \
        "{\n\t.reg .pred p;\n\t" \
        "mbarrier.try_wait.parity.acquire.cta.shared::cta.b64 p, [%1], %2;\n\t" \
        "selp.b32 %0, 1, 0, p;\n\t}" \
        : "=r"(_done) : "r"(_mbar), "r"(_parity) : "memory"); \
    if (!_done) { \
        asm volatile( \
            "{\n\t.reg .pred P1;\n\t" \
            "WAIT_LOOP_%=:\n\t" \
            "mbarrier.try_wait.parity.acquire.cta.shared::cta.b64 P1, [%0], %1, 0x989680;\n\t" \
            "@P1 bra.uni WAIT_DONE_%=;\n\t" \
            "bra.uni WAIT_LOOP_%=;\n\t" \
            "WAIT_DONE_%=:\n\t}" \
            :: "r"(_mbar), "r"(_parity) : "memory"); \
    } \
} while(0)

__device__ __forceinline__ void ldmatrix_x4(uint32_t& r0, uint32_t& r1,
                                            uint32_t& r2, uint32_t& r3, uint32_t addr) {
    asm volatile("ldmatrix.sync.aligned.m8n8.x4.shared.b16 {%0,%1,%2,%3}, [%4];"
                 : "=r"(r0), "=r"(r1), "=r"(r2), "=r"(r3) : "r"(addr));
}

__device__ __forceinline__ void imma_16832(int* c, const uint32_t* a, const uint32_t* b) {
    asm volatile(
        "mma.sync.aligned.m16n8k32.row.col.s32.s8.s8.s32 "
        "{%0,%1,%2,%3}, {%4,%5,%6,%7}, {%8,%9}, {%0,%1,%2,%3};"
        : "+r"(c[0]), "+r"(c[1]), "+r"(c[2]), "+r"(c[3])
        : "r"(a[0]), "r"(a[1]), "r"(a[2]), "r"(a[3]), "r"(b[0]), "r"(b[1]));
}

// swizzle within a [rows][128B] tile: 16B chunk XOR (row & 7)
__device__ __forceinline__ uint32_t tile_off(int row, int chunk) {
    return (uint32_t)(row * 128 + ((chunk ^ (row & 7)) << 4));
}

// ------------------------------ GEMM kernel --------------------------------
__global__ void __launch_bounds__(THREADS, 1) bgemm_imma_kernel(
    const int8_t* __restrict__ Q1,   // [M,K]
    const int8_t* __restrict__ Q2,   // [M,K]
    const int8_t* __restrict__ B,    // [N,K]
    const float*  __restrict__ s1,   // [M]
    float* __restrict__ out)
{
    extern __shared__ uint8_t smem_raw[];
    uint32_t raw = smem_u32(smem_raw);
    const uint32_t hdr   = (raw + 1023u) & ~1023u;
    const uint32_t tiles = hdr + 1024u;

    #define FULL_BAR(s)  (hdr + (uint32_t)(s) * 8u)
    #define EMPTY_BAR(s) (hdr + 64u + (uint32_t)(s) * 8u)

    const int tid  = threadIdx.x;
    const int wid  = tid >> 5;
    const int lane = tid & 31;
    const int m0 = blockIdx.x * BM;
    const int n0 = blockIdx.y * BN;

    const int warp_m = wid & 3;   // 4 warps over M: 32 rows each
    const int warp_n = wid >> 2;  // 4 warps over N: 32 cols each

    // cp.async mapping: 512 threads x 16B = 8KB/pass; every tile is 128 rows
    const int ld_row0  = tid >> 3;   // 0..63
    const int ld_chunk = tid & 7;    // 0..7

    auto load_stage = [&](int slot, int kt) {
        const uint32_t sA1 = tiles + slot * STAGE_BYTES;
        const uint32_t sA2 = sA1 + A_PLANE_BYTES;
        const uint32_t sB  = sA1 + A_TILE_BYTES;
        const int kcol = kt * BK + ld_chunk * 16;
        #pragma unroll
        for (int p = 0; p < 2; p++) {
            int row = ld_row0 + p * 64;
            uint32_t off = tile_off(row, ld_chunk);
            const size_t g = (size_t)(m0 + row) * K_DIM + kcol;
            cp_async_16(sA1 + off, Q1 + g);
            cp_async_16(sA2 + off, Q2 + g);
            cp_async_16(sB + off, B + (size_t)(n0 + row) * K_DIM + kcol);
        }
        CPASYNC_MBAR_ARRIVE_NOINC(FULL_BAR(slot));
    };

    if (tid == 0) {
        #pragma unroll
        for (int s = 0; s < STAGES; s++) {
            MBARRIER_INIT(FULL_BAR(s), THREADS);
            MBARRIER_INIT(EMPTY_BAR(s), THREADS);
        }
        asm volatile("fence.proxy.async.shared::cta;" ::: "memory");
    }
    __syncthreads();

    const int lrow = lane & 15;    // ldmatrix row within 16
    const int lsel = lane >> 4;    // ldmatrix chunk select (0/1)

    // hoisted swizzled offsets; per-kk (k32 = 32B = 2 chunks) addr = base ^ (kk<<5)
    uint32_t a_off[2], b_off[2];
    #pragma unroll
    for (int mi = 0; mi < 2; mi++)
        a_off[mi] = tile_off(warp_m * 32 + mi * 16 + lrow, lsel);
    #pragma unroll
    for (int nj = 0; nj < 2; nj++)
        b_off[nj] = tile_off(warp_n * 32 + nj * 16 + lrow, lsel);

    int acc1[2][4][4], acc2[2][4][4];
    #pragma unroll
    for (int mi = 0; mi < 2; mi++)
        #pragma unroll
        for (int ni = 0; ni < 4; ni++)
            #pragma unroll
            for (int j = 0; j < 4; j++) { acc1[mi][ni][j] = 0; acc2[mi][ni][j] = 0; }

    // prologue: fill stages 0..2
    #pragma unroll
    for (int s = 0; s < STAGES - 1; s++) {
        MBARRIER_WAIT_PARITY(EMPTY_BAR(s), 1);
        load_stage(s, s);
    }

    for (int it = 0; it < NKI; it++) {
        const int s = it & 3;
        const uint32_t sA1 = tiles + s * STAGE_BYTES;
        const uint32_t sA2 = sA1 + A_PLANE_BYTES;
        const uint32_t sB  = sA1 + A_TILE_BYTES;

        MBARRIER_WAIT_PARITY(FULL_BAR(s), (it >> 2) & 1);

        #pragma unroll
        for (int kk = 0; kk < BK / 32; kk++) {          // 4 k32 steps
            const uint32_t kx = (uint32_t)kk << 5;

            uint32_t a1[2][4], a2[2][4];
            #pragma unroll
            for (int mi = 0; mi < 2; mi++) {
                ldmatrix_x4(a1[mi][0], a1[mi][1], a1[mi][2], a1[mi][3],
                            (sA1 + a_off[mi]) ^ kx);
                ldmatrix_x4(a2[mi][0], a2[mi][1], a2[mi][2], a2[mi][3],
                            (sA2 + a_off[mi]) ^ kx);
            }
            uint32_t b[4][2];
            #pragma unroll
            for (int nj = 0; nj < 2; nj++) {
                uint32_t r0, r1, r2, r3;
                ldmatrix_x4(r0, r1, r2, r3, (sB + b_off[nj]) ^ kx);
                b[nj * 2 + 0][0] = r0; b[nj * 2 + 1][0] = r1;
                b[nj * 2 + 0][1] = r2; b[nj * 2 + 1][1] = r3;
            }

            if (kk == BK / 32 - 1) MBARRIER_ARRIVE(EMPTY_BAR(s));

            #pragma unroll
            for (int mi = 0; mi < 2; mi++)
                #pragma unroll
                for (int ni = 0; ni < 4; ni++) {
                    imma_16832(acc1[mi][ni], a1[mi], b[ni]);
                    imma_16832(acc2[mi][ni], a2[mi], b[ni]);
                }
        }

        const int kt = it + STAGES - 1;
        if (kt < NKI) {
            const int ps = kt & 3;
            MBARRIER_WAIT_PARITY(EMPTY_BAR(ps), ((kt >> 2) & 1) ^ 1);
            load_stage(ps, kt);
        }
    }

    // ------------------------------ epilogue -------------------------------
    const int tq = lane >> 2;       // 0..7
    const int tp = lane & 3;        // col pair
    #pragma unroll
    for (int mi = 0; mi < 2; mi++) {
        const int rbase = m0 + warp_m * 32 + mi * 16 + tq;
        const float sc0 = s1[rbase];
        const float sc1 = s1[rbase + 8];
        #pragma unroll
        for (int ni = 0; ni < 4; ni++) {
            int c = n0 + warp_n * 32 + ni * 8 + tp * 2;
            float2 v0, v1;
            v0.x = ((float)acc1[mi][ni][0] + (float)acc2[mi][ni][0] * (1.f/256.f)) * sc0;
            v0.y = ((float)acc1[mi][ni][1] + (float)acc2[mi][ni][1] * (1.f/256.f)) * sc0;
            v1.x = ((float)acc1[mi][ni][2] + (float)acc2[mi][ni][2] * (1.f/256.f)) * sc1;
            v1.y = ((float)acc1[mi][ni][3] + (float)acc2[mi][ni][3] * (1.f/256.f)) * sc1;
            *reinterpret_cast<float2*>(out + (size_t)rbase * N_DIM + c) = v0;
            *reinterpret_cast<float2*>(out + (size_t)(rbase + 8) * N_DIM + c) = v1;
        }
    }
}

// ------------------------------- host side --------------------------------
extern "C" void kernel_launch(void* const* d_in, const int* in_sizes, int n_in,
                              void* d_out, int out_size)
{
    const float* x = (const float*)d_in[0];
    const float* w = (const float*)d_in[1];
    float* out = (float*)d_out;

    void *q1p = nullptr, *q2p = nullptr, *wbtp = nullptr, *s1p = nullptr;
    cudaGetSymbolAddress(&q1p, g_q1);
    cudaGetSymbolAddress(&q2p, g_q2);
    cudaGetSymbolAddress(&wbtp, g_wbt);
    cudaGetSymbolAddress(&s1p, g_s1);

    quant_x_kernel<<<M_DIM, 256>>>((const float4*)x, (char4*)q1p,
                                   (char4*)q2p, (float*)s1p);
    {
        dim3 gw(N_DIM / 32, K_DIM / 32), bw(32, 8);
        cvt_w_kernel<<<gw, bw>>>(w, (int8_t*)wbtp);
    }

    // pad launch so ncu's "-s 5 -c 1" window lands on the GEMM
    prof_pad_kernel<<<1, 32>>>();

    cudaFuncSetAttribute(bgemm_imma_kernel,
                         cudaFuncAttributeMaxDynamicSharedMemorySize, SMEM_DYN);

    dim3 grid(M_DIM / BM, N_DIM / BN);  // (64, 32)
    bgemm_imma_kernel<<<grid, THREADS, SMEM_DYN>>>(
        (const int8_t*)q1p, (const int8_t*)q2p, (const int8_t*)wbtp,
        (const float*)s1p, out);
}

// round 9
// speedup vs baseline: 4.0911x; 4.0911x over previous
#include <cuda_runtime.h>
#include <cuda_fp16.h>
#include <cstdint>

// ---------------------------------------------------------------------------
// out[8192,4096] = x[8192,4096]_fp32 @ sign(fp16(w[4096,4096]))
//
// R9: fp16-ACCUMULATE experiment. R8 proved the pipeline can drive the tensor
// pipe to 95%; the fp16/f32acc path is walled at rt~11.7 cyc (f32-acc
// penalty). Chunked f16-acc: 4 chained m16n8k16.f16 MMAs per k-iter (K=64),
// flushed into fp32 registers each iteration (added rel err ~2.5e-4).
// CTA 128x128, 256 threads, 4-stage cp.async + mbarrier pipeline (R7).
// ---------------------------------------------------------------------------

#define M_DIM 8192
#define N_DIM 4096
#define K_DIM 4096

#define BM 128
#define BN 128
#define BK 64
#define STAGES 4
#define THREADS 256
#define NKI (K_DIM / BK)   // 64

#define A_TILE_BYTES (BM * BK * 2)            // 16384
#define B_TILE_BYTES (BN * BK * 2)            // 16384
#define STAGE_BYTES  (A_TILE_BYTES + B_TILE_BYTES)   // 32768
#define SMEM_DYN     (1024 + 1024 + STAGES * STAGE_BYTES)  // 133120

// ------------------------------ scratch -----------------------------------
__device__ __align__(1024) __half g_xh[(size_t)M_DIM * K_DIM];   // 64 MB
__device__ __align__(1024) __half g_wbt[(size_t)N_DIM * K_DIM];  // 32 MB

// --------------------------- convert kernels -------------------------------
__global__ void cvt_x_kernel(const float4* __restrict__ x, uint2* __restrict__ xh, int n4) {
    int i = blockIdx.x * blockDim.x + threadIdx.x;
    if (i >= n4) return;
    float4 v = x[i];
    __half2 a = __floats2half2_rn(v.x, v.y);
    __half2 b = __floats2half2_rn(v.z, v.w);
    uint2 o;
    o.x = *reinterpret_cast<uint32_t*>(&a);
    o.y = *reinterpret_cast<uint32_t*>(&b);
    xh[i] = o;
}

// w[K,N] fp32 -> wbt[N,K] fp16 with value sign(fp16(w)) (sign(0) = 0)
__global__ void cvt_w_kernel(const float* __restrict__ w, __half* __restrict__ wbt) {
    __shared__ __half tile[32][33];
    int n0 = blockIdx.x * 32;
    int k0 = blockIdx.y * 32;
    int tx = threadIdx.x, ty = threadIdx.y;
    #pragma unroll
    for (int j = ty; j < 32; j += 8) {
        float v = w[(size_t)(k0 + j) * N_DIM + n0 + tx];
        float hf = __half2float(__float2half_rn(v));  // exact fp16 round trip
        float s = (hf > 0.f) ? 1.f : ((hf < 0.f) ? -1.f : 0.f);
        tile[j][tx] = __float2half_rn(s);
    }
    __syncthreads();
    #pragma unroll
    for (int j = ty; j < 32; j += 8) {
        wbt[(size_t)(n0 + j) * K_DIM + k0 + tx] = tile[tx][j];
    }
}

// dummy launch to keep ncu's -s window on the GEMM (position 3)
__global__ void prof_pad_kernel() {}

// ------------------------------ PTX helpers -------------------------------
__device__ __forceinline__ uint32_t smem_u32(const void* p) {
    uint32_t a;
    asm("{ .reg .u64 t; cvta.to.shared.u64 t, %1; cvt.u32.u64 %0, t; }"
        : "=r"(a) : "l"(p));
    return a;
}

__device__ __forceinline__ void cp_async_16(uint32_t smem_dst, const void* gmem_src) {
    asm volatile("cp.async.cg.shared.global [%0], [%1], 16;"
                 :: "r"(smem_dst), "l"(gmem_src));
}

#define MBARRIER_INIT(addr, count) \
    asm volatile("mbarrier.init.shared.b64 [%0], %1;" \
                 :: "r"((uint32_t)(addr)), "r"((uint32_t)(count)) : "memory")

#define MBARRIER_ARRIVE(addr) \
    asm volatile("mbarrier.arrive.shared.b64 _, [%0];" \
                 :: "r"((uint32_t)(addr)) : "memory")

#define CPASYNC_MBAR_ARRIVE_NOINC(addr) \
    asm volatile("cp.async.mbarrier.arrive.noinc.shared.b64 [%0];" \
                 :: "r"((uint32_t)(addr)) : "memory")

#define MBARRIER_WAIT_PARITY(mbar_smem_addr, phase_parity) do { \
    uint32_t _mbar = (uint32_t)(mbar_smem_addr); \
    uint32_t _parity = (uint32_t)(phase_parity); \
    uint32_t _done; \
    asm volatile( \
        "{\n\t.reg .pred p;\n\t" \
        "mbarrier.try_wait.parity.acquire.cta.shared::cta.b64 p, [%1], %2;\n\t" \
        "selp.b32 %0, 1, 0, p;\n\t}" \
        : "=r"(_done) : "r"(_mbar), "r"(_parity) : "memory"); \
    if (!_done) { \
        asm volatile( \
            "{\n\t.reg .pred P1;\n\t" \
            "WAIT_LOOP_%=:\n\t" \
            "mbarrier.try_wait.parity.acquire.cta.shared::cta.b64 P1, [%0], %1, 0x989680;\n\t" \
            "@P1 bra.uni WAIT_DONE_%=;\n\t" \
            "bra.uni WAIT_LOOP_%=;\n\t" \
            "WAIT_DONE_%=:\n\t}" \
            :: "r"(_mbar), "r"(_parity) : "memory"); \
    } \
} while(0)

__device__ __forceinline__ void ldmatrix_x4(uint32_t& r0, uint32_t& r1,
                                            uint32_t& r2, uint32_t& r3, uint32_t addr) {
    asm volatile("ldmatrix.sync.aligned.m8n8.x4.shared.b16 {%0,%1,%2,%3}, [%4];"
                 : "=r"(r0), "=r"(r1), "=r"(r2), "=r"(r3) : "r"(addr));
}

// fp16-accumulate MMA: C/D are 2 regs of f16x2
__device__ __forceinline__ void mma_16816_f16(uint32_t* c, const uint32_t* a,
                                              const uint32_t* b) {
    asm volatile(
        "mma.sync.aligned.m16n8k16.row.col.f16.f16.f16.f16 "
        "{%0,%1}, {%2,%3,%4,%5}, {%6,%7}, {%0,%1};"
        : "+r"(c[0]), "+r"(c[1])
        : "r"(a[0]), "r"(a[1]), "r"(a[2]), "r"(a[3]), "r"(b[0]), "r"(b[1]));
}

// swizzle within a [rows][BK] fp16 tile, 128B rows: 16B chunk XOR (row & 7)
__device__ __forceinline__ uint32_t tile_off(int row, int chunk) {
    return (uint32_t)(row * 128 + ((chunk ^ (row & 7)) << 4));
}

// ------------------------------ GEMM kernel --------------------------------
__global__ void __launch_bounds__(THREADS, 1) bgemm_mma_kernel(
    const __half* __restrict__ A,   // [M,K]
    const __half* __restrict__ B,   // [N,K]
    float* __restrict__ out)
{
    extern __shared__ uint8_t smem_raw[];
    uint32_t raw = smem_u32(smem_raw);
    const uint32_t hdr   = (raw + 1023u) & ~1023u;
    const uint32_t tiles = hdr + 1024u;

    #define FULL_BAR(s)  (hdr + (uint32_t)(s) * 8u)
    #define EMPTY_BAR(s) (hdr + 64u + (uint32_t)(s) * 8u)

    const int tid  = threadIdx.x;
    const int wid  = tid >> 5;
    const int lane = tid & 31;
    const int m0 = blockIdx.x * BM;
    const int n0 = blockIdx.y * BN;

    const int warp_m = wid & 3;   // 4 warps over M: 32 rows each
    const int warp_n = wid >> 2;  // 2 warps over N: 64 cols each

    // cp.async mapping: 256 threads x 16B; each tile 128 rows x 8 chunks
    const int ld_row0  = tid >> 3;   // 0..31
    const int ld_chunk = tid & 7;    // 0..7

    auto load_stage = [&](int slot, int kt) {
        const uint32_t sA = tiles + slot * STAGE_BYTES;
        const uint32_t sB = sA + A_TILE_BYTES;
        const int kcol = kt * BK + ld_chunk * 8;
        #pragma unroll
        for (int p = 0; p < 4; p++) {
            int row = ld_row0 + p * 32;
            uint32_t off = tile_off(row, ld_chunk);
            cp_async_16(sA + off, A + (size_t)(m0 + row) * K_DIM + kcol);
            cp_async_16(sB + off, B + (size_t)(n0 + row) * K_DIM + kcol);
        }
        CPASYNC_MBAR_ARRIVE_NOINC(FULL_BAR(slot));
    };

    if (tid == 0) {
        #pragma unroll
        for (int s = 0; s < STAGES; s++) {
            MBARRIER_INIT(FULL_BAR(s), THREADS);
            MBARRIER_INIT(EMPTY_BAR(s), THREADS);
        }
        asm volatile("fence.proxy.async.shared::cta;" ::: "memory");
    }
    __syncthreads();

    const int lrow = lane & 15;
    const int lsel = lane >> 4;

    uint32_t a_off[2], b_off[4];
    #pragma unroll
    for (int mi = 0; mi < 2; mi++)
        a_off[mi] = tile_off(warp_m * 32 + mi * 16 + lrow, lsel);
    #pragma unroll
    for (int nj = 0; nj < 4; nj++)
        b_off[nj] = tile_off(warp_n * 64 + nj * 16 + lrow, lsel);

    float acc[2][8][4];
    #pragma unroll
    for (int mi = 0; mi < 2; mi++)
        #pragma unroll
        for (int ni = 0; ni < 8; ni++)
            #pragma unroll
            for (int j = 0; j < 4; j++) acc[mi][ni][j] = 0.f;

    // prologue
    #pragma unroll
    for (int s = 0; s < STAGES - 1; s++) {
        MBARRIER_WAIT_PARITY(EMPTY_BAR(s), 1);
        load_stage(s, s);
    }

    for (int it = 0; it < NKI; it++) {
        const int s = it & 3;
        const uint32_t sA = tiles + s * STAGE_BYTES;
        const uint32_t sB = sA + A_TILE_BYTES;

        MBARRIER_WAIT_PARITY(FULL_BAR(s), (it >> 2) & 1);

        // fp16 chunk accumulators (zeroed each k-iter)
        uint32_t acch[2][8][2];
        #pragma unroll
        for (int mi = 0; mi < 2; mi++)
            #pragma unroll
            for (int ni = 0; ni < 8; ni++) {
                acch[mi][ni][0] = 0u; acch[mi][ni][1] = 0u;
            }

        #pragma unroll
        for (int kk = 0; kk < BK / 16; kk++) {
            const uint32_t kx = (uint32_t)kk << 5;

            uint32_t a[2][4];
            #pragma unroll
            for (int mi = 0; mi < 2; mi++)
                ldmatrix_x4(a[mi][0], a[mi][1], a[mi][2], a[mi][3],
                            (sA + a_off[mi]) ^ kx);
            uint32_t b[8][2];
            #pragma unroll
            for (int nj = 0; nj < 4; nj++) {
                uint32_t r0, r1, r2, r3;
                ldmatrix_x4(r0, r1, r2, r3, (sB + b_off[nj]) ^ kx);
                b[nj * 2 + 0][0] = r0; b[nj * 2 + 1][0] = r1;
                b[nj * 2 + 0][1] = r2; b[nj * 2 + 1][1] = r3;
            }

            if (kk == BK / 16 - 1) MBARRIER_ARRIVE(EMPTY_BAR(s));

            #pragma unroll
            for (int mi = 0; mi < 2; mi++)
                #pragma unroll
                for (int ni = 0; ni < 8; ni++)
                    mma_16816_f16(acch[mi][ni], a[mi], b[ni]);
        }

        // flush fp16 chunk sums into fp32 accumulators (fma/alu pipes idle)
        #pragma unroll
        for (int mi = 0; mi < 2; mi++)
            #pragma unroll
            for (int ni = 0; ni < 8; ni++) {
                float2 f0 = __half22float2(
                    *reinterpret_cast<__half2*>(&acch[mi][ni][0]));
                float2 f1 = __half22float2(
                    *reinterpret_cast<__half2*>(&acch[mi][ni][1]));
                acc[mi][ni][0] += f0.x; acc[mi][ni][1] += f0.y;
                acc[mi][ni][2] += f1.x; acc[mi][ni][3] += f1.y;
            }

        const int kt = it + STAGES - 1;
        if (kt < NKI) {
            const int ps = kt & 3;
            MBARRIER_WAIT_PARITY(EMPTY_BAR(ps), ((kt >> 2) & 1) ^ 1);
            load_stage(ps, kt);
        }
    }

    // ------------------------------ epilogue -------------------------------
    const int tq = lane >> 2;
    const int tp = lane & 3;
    #pragma unroll
    for (int mi = 0; mi < 2; mi++) {
        #pragma unroll
        for (int ni = 0; ni < 8; ni++) {
            int r = m0 + warp_m * 32 + mi * 16 + tq;
            int c = n0 + warp_n * 64 + ni * 8 + tp * 2;
            float2 v0 = make_float2(acc[mi][ni][0], acc[mi][ni][1]);
            float2 v1 = make_float2(acc[mi][ni][2], acc[mi][ni][3]);
            *reinterpret_cast<float2*>(out + (size_t)r * N_DIM + c) = v0;
            *reinterpret_cast<float2*>(out + (size_t)(r + 8) * N_DIM + c) = v1;
        }
    }
}

// ------------------------------- host side --------------------------------
extern "C" void kernel_launch(void* const* d_in, const int* in_sizes, int n_in,
                              void* d_out, int out_size)
{
    const float* x = (const float*)d_in[0];
    const float* w = (const float*)d_in[1];
    float* out = (float*)d_out;

    void *xh_ptr = nullptr, *wbt_ptr = nullptr;
    cudaGetSymbolAddress(&xh_ptr, g_xh);
    cudaGetSymbolAddress(&wbt_ptr, g_wbt);

    {
        int n4 = (M_DIM * K_DIM) / 4;
        cvt_x_kernel<<<(n4 + 255) / 256, 256>>>((const float4*)x, (uint2*)xh_ptr, n4);
        dim3 gw(N_DIM / 32, K_DIM / 32), bw(32, 8);
        cvt_w_kernel<<<gw, bw>>>(w, (__half*)wbt_ptr);
    }

    // pad launch so ncu's "-s 5 -c 1" window lands on the GEMM
    prof_pad_kernel<<<1, 32>>>();

    cudaFuncSetAttribute(bgemm_mma_kernel,
                         cudaFuncAttributeMaxDynamicSharedMemorySize, SMEM_DYN);

    dim3 grid(M_DIM / BM, N_DIM / BN);  // (64, 32)
    bgemm_mma_kernel<<<grid, THREADS, SMEM_DYN>>>(
        (const __half*)xh_ptr, (const __half*)wbt_ptr, out);
}